// round 7
// baseline (speedup 1.0000x reference)
#include <cuda_runtime.h>
#include <cuda_fp16.h>

#define D 4096
#define NSTEPS 50
#define NCTA 147
#define ROWS_PER_CTA 28
#define CACHED_ROWS 12           // rows per CTA held in SMEM (192 KB)
#define NTHREADS 1024

// Interleaved fp16 matrices: g_AB[r*2D + 2j] = A[r][j], [.. + 1] = B[r][j].
__device__ __align__(16) __half g_AB[(size_t)2 * D * D];
__device__ unsigned int g_bar;   // global step barrier counter (monotonic per launch)

// ---------------------------------------------------------------------------
// prep: interleave A,B into fp16 pairs; reset the barrier counter.
// ---------------------------------------------------------------------------
__global__ void __launch_bounds__(256) prep_kernel(const float* __restrict__ A,
                                                   const float* __restrict__ B) {
    if (blockIdx.x == 0 && threadIdx.x == 0) g_bar = 0;
    size_t i = (size_t)blockIdx.x * blockDim.x + threadIdx.x;  // float4 index
    float4 a = ((const float4*)A)[i];
    float4 b = ((const float4*)B)[i];
    uint4 o;
    __half2 p;
    p = __floats2half2_rn(a.x, b.x); o.x = *(unsigned int*)&p;
    p = __floats2half2_rn(a.y, b.y); o.y = *(unsigned int*)&p;
    p = __floats2half2_rn(a.z, b.z); o.z = *(unsigned int*)&p;
    p = __floats2half2_rn(a.w, b.w); o.w = *(unsigned int*)&p;
    ((uint4*)g_AB)[i] = o;
}

// Pack two f32 into a 64-bit register pair (for f32x2 ops)
__device__ __forceinline__ unsigned long long packf2(float lo, float hi) {
    unsigned long long r;
    asm("mov.b64 %0, {%1, %2};" : "=l"(r) : "f"(lo), "f"(hi));
    return r;
}

// acc(f32x2) += cvt_f32x2(m: half2 (a,b)) * td(f32x2 (t,d))   — ONE FFMA2
__device__ __forceinline__ void fma2AB(unsigned int m, unsigned long long td,
                                       unsigned long long& acc) {
    asm("{\n\t"
        ".reg .b16 l, h;\n\t"
        ".reg .f32 fa, fb;\n\t"
        ".reg .b64 ab;\n\t"
        "mov.b32 {l, h}, %1;\n\t"
        "cvt.f32.f16 fa, l;\n\t"
        "cvt.f32.f16 fb, h;\n\t"
        "mov.b64 ab, {fa, fb};\n\t"
        "fma.rn.f32x2 %0, ab, %2, %0;\n\t"
        "}" : "+l"(acc) : "r"(m), "l"(td));
}

// process one uint4 (4 (a,b) pairs) of a row against shared packed td0..td3
__device__ __forceinline__ void dotAB2(uint4 m,
                                       unsigned long long td0, unsigned long long td1,
                                       unsigned long long td2, unsigned long long td3,
                                       unsigned long long& acc) {
    fma2AB(m.x, td0, acc);
    fma2AB(m.y, td1, acc);
    fma2AB(m.z, td2, acc);
    fma2AB(m.w, td3, acc);
}

__device__ __forceinline__ float acc_sum(unsigned long long acc) {
    float lo, hi;
    asm("mov.b64 {%0, %1}, %2;" : "=f"(lo), "=f"(hi) : "l"(acc));
    return lo + hi;   // Sum(a*t) + Sum(b*d)
}

// ---------------------------------------------------------------------------
// Persistent recurrence kernel: 147 CTAs x 1024 threads, 28 rows/CTA.
// Rows 0..11 cached in SMEM once; rows 12..27 stream from L2.  Warp (rg,ks):
// 4-row group x 1024-elem K-segment.  Inner loop: half2 (a,b) -> f32 pair,
// single fma.rn.f32x2 against packed (theta, delta) shared across 4 rows.
// ---------------------------------------------------------------------------
__global__ void __launch_bounds__(NTHREADS, 1) rnn_kernel(const float* __restrict__ init,
                                                          float* __restrict__ out) {
    extern __shared__ char smem[];
    float4* s_t    = (float4*)smem;                    // theta_t   (16 KB)
    float4* s_d    = (float4*)(smem + 16384);          // delta     (16 KB)
    float*  s_part = (float*)(smem + 32768);           // partials  (512 B)
    uint4*  s_mat  = (uint4*)(smem + 33280);           // cached rows (192 KB)

    const int tid  = threadIdx.x;
    const int warp = tid >> 5;
    const int lane = tid & 31;
    const int rg   = warp >> 2;                        // 0..7 (7 idle)
    const int ks   = warp & 3;                         // 0..3
    const int row_base = blockIdx.x * ROWS_PER_CTA;
    const int row0 = row_base + rg * 4;
    const bool rowOK  = (rg < 7) && (row0 < D);
    const bool cached = (rg < CACHED_ROWS / 4);        // rg 0..2 -> SMEM rows
    const int seg = ks * 256;                          // float4 offset of segment

    // Preload cached rows into SMEM (once).  Clamp OOB rows of the last CTA.
#pragma unroll
    for (int it = 0; it < CACHED_ROWS; ++it) {
        int src_row = row_base + it;
        if (src_row >= D) src_row = D - 1;
        s_mat[it * 1024 + tid] = ((const uint4*)g_AB)[(size_t)src_row * 1024 + tid];
    }

    // Streamed-row pointers (rg >= 3)
    const uint4* r0 = (const uint4*)g_AB + (size_t)min(row0 + 0, D - 1) * 1024;
    const uint4* r1 = (const uint4*)g_AB + (size_t)min(row0 + 1, D - 1) * 1024;
    const uint4* r2 = (const uint4*)g_AB + (size_t)min(row0 + 2, D - 1) * 1024;
    const uint4* r3 = (const uint4*)g_AB + (size_t)min(row0 + 3, D - 1) * 1024;
    // Cached-row pointers (rg < 3)
    const uint4* c0 = s_mat + (size_t)(rg * 4 + 0) * 1024;
    const uint4* c1 = s_mat + (size_t)(rg * 4 + 1) * 1024;
    const uint4* c2 = s_mat + (size_t)(rg * 4 + 2) * 1024;
    const uint4* c3 = s_mat + (size_t)(rg * 4 + 3) * 1024;

    // Prologue: s_t holds theta_{-1} = init_seq[0]
    s_t[tid] = ((const float4*)init)[tid];

    for (int t = 0; t < NSTEPS; ++t) {
        // Stage theta_t; delta = theta_t - theta_{t-1} (prev step's s_t)
        const float* th1 = (t == 0) ? init + D : out + (size_t)(t - 1) * D;
        float4 nt = __ldcg((const float4*)th1 + tid);
        float4 pt = s_t[tid];
        s_t[tid] = nt;
        s_d[tid] = make_float4(nt.x - pt.x, nt.y - pt.y, nt.z - pt.z, nt.w - pt.w);
        __syncthreads();

        if (rowOK) {
            unsigned long long acc0 = 0, acc1 = 0, acc2 = 0, acc3 = 0;
            if (cached) {
#pragma unroll 2
                for (int i = 0; i < 8; ++i) {
                    int idx = seg + i * 32 + lane;
                    float4 t4 = s_t[idx];
                    float4 d4 = s_d[idx];
                    unsigned long long td0 = packf2(t4.x, d4.x);
                    unsigned long long td1 = packf2(t4.y, d4.y);
                    unsigned long long td2 = packf2(t4.z, d4.z);
                    unsigned long long td3 = packf2(t4.w, d4.w);
                    dotAB2(c0[idx], td0, td1, td2, td3, acc0);
                    dotAB2(c1[idx], td0, td1, td2, td3, acc1);
                    dotAB2(c2[idx], td0, td1, td2, td3, acc2);
                    dotAB2(c3[idx], td0, td1, td2, td3, acc3);
                }
            } else {
#pragma unroll 2
                for (int i = 0; i < 8; ++i) {
                    int idx = seg + i * 32 + lane;
                    float4 t4 = s_t[idx];
                    float4 d4 = s_d[idx];
                    uint4 m0 = r0[idx];
                    uint4 m1 = r1[idx];
                    uint4 m2 = r2[idx];
                    uint4 m3 = r3[idx];
                    unsigned long long td0 = packf2(t4.x, d4.x);
                    unsigned long long td1 = packf2(t4.y, d4.y);
                    unsigned long long td2 = packf2(t4.z, d4.z);
                    unsigned long long td3 = packf2(t4.w, d4.w);
                    dotAB2(m0, td0, td1, td2, td3, acc0);
                    dotAB2(m1, td0, td1, td2, td3, acc1);
                    dotAB2(m2, td0, td1, td2, td3, acc2);
                    dotAB2(m3, td0, td1, td2, td3, acc3);
                }
            }
            float v0 = acc_sum(acc0);
            float v1 = acc_sum(acc1);
            float v2 = acc_sum(acc2);
            float v3 = acc_sum(acc3);
#pragma unroll
            for (int off = 16; off; off >>= 1) {
                v0 += __shfl_xor_sync(0xffffffffu, v0, off);
                v1 += __shfl_xor_sync(0xffffffffu, v1, off);
                v2 += __shfl_xor_sync(0xffffffffu, v2, off);
                v3 += __shfl_xor_sync(0xffffffffu, v3, off);
            }
            if (lane == 0) {
                s_part[(rg * 4 + 0) * 4 + ks] = v0;
                s_part[(rg * 4 + 1) * 4 + ks] = v1;
                s_part[(rg * 4 + 2) * 4 + ks] = v2;
                s_part[(rg * 4 + 3) * 4 + ks] = v3;
            }
        }
        __syncthreads();

        // Combine K-segment partials (deterministic order) and publish the row
        if (tid < ROWS_PER_CTA) {
            int row = row_base + tid;
            if (row < D) {
                float v = (s_part[tid * 4 + 0] + s_part[tid * 4 + 1]) +
                          (s_part[tid * 4 + 2] + s_part[tid * 4 + 3]);
                __stcg(out + (size_t)t * D + row, v);
            }
        }
        __syncthreads();

        // Device-wide step barrier (all 147 CTAs co-resident: 1 CTA/SM).
        // Single release fence: syncthreads ordered this CTA's stores before
        // tid0's fence, so one __threadfence suffices for gpu-wide release.
        if (tid == 0) {
            __threadfence();              // release all this CTA's rows
            atomicAdd(&g_bar, 1u);
            unsigned int target = (unsigned int)(t + 1) * NCTA;
            while (*(volatile unsigned int*)&g_bar < target) { }
            __threadfence();              // acquire
        }
        __syncthreads();
    }
}

// ---------------------------------------------------------------------------
// Launch: prep (convert + barrier reset), then ONE persistent kernel with
// opt-in 224.5 KB dynamic SMEM.
// ---------------------------------------------------------------------------
extern "C" void kernel_launch(void* const* d_in, const int* in_sizes, int n_in,
                              void* d_out, int out_size) {
    const float* init = (const float*)d_in[0];  // [2, D]
    const float* A    = (const float*)d_in[1];  // [D, D]
    const float* B    = (const float*)d_in[2];  // [D, D]
    float* out = (float*)d_out;                 // [NSTEPS, D]

    const int smem_bytes = 33280 + CACHED_ROWS * 1024 * 16;  // 229,888 B
    cudaFuncSetAttribute(rnn_kernel, cudaFuncAttributeMaxDynamicSharedMemorySize,
                         smem_bytes);

    prep_kernel<<<(D * (size_t)D / 4) / 256, 256>>>(A, B);
    rnn_kernel<<<NCTA, NTHREADS, smem_bytes>>>(init, out);
}